// round 7
// baseline (speedup 1.0000x reference)
#include <cuda_runtime.h>
#include <cuda_bf16.h>

#define K_ 16
#define P_ 27000

// Even tile: x[b, c=0..2, h0:h0+3, 0:32, 0:32], strides c=3072,h=1024,w=32,d=1
// Odd tile : same data shifted by one float (odd[j] = even[j+1])
#define TILE_F 9216              // floats per tile copy
#define DYN_F  (2 * TILE_F)      // 18432 floats = 73728 B dynamic smem

__constant__ float c_MOPS[64] = {
    0,0,0,0,   0,0,0,1,   0,1,0,-1,  0,1,0,0,
    0,0,1,-1,  0,0,1,0,   0,1,1,-2,  0,1,1,-1,
    1,-1,-1,1, 1,-1,-1,2, 1,0,-1,0,  1,0,-1,1,
    1,-1,0,0,  1,-1,0,1,  1,0,0,-1,  1,0,0,0
};

typedef unsigned long long ull;

__device__ __forceinline__ ull fma2(ull a, ull b, ull c) {
    ull d;
    asm("fma.rn.f32x2 %0, %1, %2, %3;" : "=l"(d) : "l"(a), "l"(b), "l"(c));
    return d;
}
// c0 + c1*a + c2*b + c3*a*b  (packed over 2 outputs)
__device__ __forceinline__ ull node2(ull c0, ull c1, ull c2, ull c3, ull a, ull b) {
    return fma2(b, fma2(c3, a, c2), fma2(c1, a, c0));
}
__device__ __forceinline__ ull lds64(unsigned a) {
    ull v;
    asm("ld.shared.b64 %0, [%1];" : "=l"(v) : "r"(a));
    return v;
}
__device__ __forceinline__ void ldcoef(unsigned a, ull& c0, ull& c1, ull& c2, ull& c3) {
    asm("ld.shared.v2.u64 {%0,%1}, [%2];" : "=l"(c0), "=l"(c1) : "r"(a));
    asm("ld.shared.v2.u64 {%0,%1}, [%2];" : "=l"(c2), "=l"(c3) : "r"(a + 16));
}

extern __shared__ float s_dyn[];  // [0..9215]=even tile, [9216..18431]=odd tile

__global__ __launch_bounds__(256, 3)
void logic_fused(const float* __restrict__ x,
                 const int* __restrict__ ia, const int* __restrict__ ib,
                 const float* __restrict__ w0, const float* __restrict__ w1,
                 const float* __restrict__ w2, const float* __restrict__ w3,
                 const float* __restrict__ w4,
                 float* __restrict__ out)
{
    __shared__ float4 s_cp[31][2];   // per node: (c0,c0,c1,c1) , (c2,c2,c3,c3)
    __shared__ int    s_loffA[16];   // leaf byte offsets (odd-parity redirected)
    __shared__ int    s_loffB[16];

    const int h0 = blockIdx.x;   // 0..29
    const int k  = blockIdx.y;
    const int b  = blockIdx.z;
    const int t  = threadIdx.x;

    // ---- prep: tree coefficients, pre-duplicated for f32x2 (threads 0..30) ----
    if (t < 31) {
        const float* wp; int n;
        if      (t < 16) { wp = w0; n = t;      }
        else if (t < 24) { wp = w1; n = t - 16; }
        else if (t < 28) { wp = w2; n = t - 24; }
        else if (t < 30) { wp = w3; n = t - 28; }
        else             { wp = w4; n = 0;      }
        const float* row = wp + (n * K_ + k) * 16;
        float r[16];
        float m = -1e30f;
        #pragma unroll
        for (int o = 0; o < 16; o++) { r[o] = row[o]; m = fmaxf(m, r[o]); }
        float sum = 0.f;
        #pragma unroll
        for (int o = 0; o < 16; o++) { r[o] = __expf(r[o] - m); sum += r[o]; }
        float inv = 1.0f / sum;
        float c0 = 0.f, c1 = 0.f, c2 = 0.f, c3 = 0.f;
        #pragma unroll
        for (int o = 0; o < 16; o++) {
            float p = r[o] * inv;
            c0 = fmaf(p, c_MOPS[4*o + 0], c0);
            c1 = fmaf(p, c_MOPS[4*o + 1], c1);
            c2 = fmaf(p, c_MOPS[4*o + 2], c2);
            c3 = fmaf(p, c_MOPS[4*o + 3], c3);
        }
        s_cp[t][0] = make_float4(c0, c0, c1, c1);
        s_cp[t][1] = make_float4(c2, c2, c3, c3);
    }
    // ---- prep: leaf offsets (threads 32..63); redirect odd parity to odd tile ----
    if (t >= 32 && t < 64) {
        int u = t - 32;
        const int* src = (u < 16) ? ia : ib;
        int s = u & 15;
        int base = (k * P_ * 16 + s) * 4;
        int h = src[base + 0];
        int w = src[base + 1];
        int d = src[base + 2];
        int c = src[base + 3];
        int lin = c * 3072 + h * 1024 + w * 32 + d;
        int eff = (lin & 1) ? (TILE_F + lin - 1) : lin;   // odd -> shifted tile
        if (u < 16) s_loffA[s] = eff * 4;                  // byte offsets
        else        s_loffB[s] = eff * 4;
    }

    // ---- tile load: even copy + shifted odd copy (shuffle for the seam) ----
    {
        const float* src = x + b * 98304 + h0 * 1024;   // x[b,0,h0,0,0]
        float* ev = s_dyn;
        float* od = s_dyn + TILE_F;
        #pragma unroll
        for (int c = 0; c < 3; c++) {
            #pragma unroll
            for (int j = 0; j < 3; j++) {
                int idx = j * 256 + t;                  // float4 id within slab
                int e   = idx * 4;
                float4 v = *reinterpret_cast<const float4*>(src + c * 32768 + e);
                float nxt = __shfl_down_sync(0xffffffffu, v.x, 1);
                *reinterpret_cast<float4*>(ev + c * 3072 + e) = v;
                // odd[e+m] = even[e+m+1]; slot e+3 for lane31 is garbage but
                // lands at d==31 which no gather ever reads.
                *reinterpret_cast<float4*>(od + c * 3072 + e) =
                    make_float4(v.y, v.z, v.w, nxt);
            }
        }
    }
    __syncthreads();

    // ---- compute: each thread handles 2 output pairs (4 outputs) ----
    // pair q in [0,450): lw = q/15, dp = q%15 -> outputs (lw, 2dp) & (lw, 2dp+1)
    const int q0 = t;
    const int q1v = t + 256;
    const int q1 = min(q1v, 449);

    const int lw0 = q0 / 15, dp0 = q0 - lw0 * 15;
    const int lw1 = q1 / 15, dp1 = q1 - lw1 * 15;

    const unsigned tb  = (unsigned)__cvta_generic_to_shared(s_dyn);
    const unsigned cpb = (unsigned)__cvta_generic_to_shared(&s_cp[0][0]);
    unsigned pb[2];
    pb[0] = tb + 4u * (unsigned)(lw0 * 32 + 2 * dp0);
    pb[1] = tb + 4u * (unsigned)(lw1 * 32 + 2 * dp1);

    ull t2[2][4];
    #pragma unroll
    for (int n2 = 0; n2 < 4; n2++) {
        // coefs: leaves 4n2..4n2+3, L1 nodes 16+2n2..17+2n2, L2 node 24+n2
        ull C[7][4];
        #pragma unroll
        for (int i = 0; i < 4; i++)
            ldcoef(cpb + (unsigned)(4 * n2 + i) * 32u, C[i][0], C[i][1], C[i][2], C[i][3]);
        ldcoef(cpb + (unsigned)(16 + 2 * n2) * 32u, C[4][0], C[4][1], C[4][2], C[4][3]);
        ldcoef(cpb + (unsigned)(17 + 2 * n2) * 32u, C[5][0], C[5][1], C[5][2], C[5][3]);
        ldcoef(cpb + (unsigned)(24 + n2) * 32u,     C[6][0], C[6][1], C[6][2], C[6][3]);

        int oa0 = s_loffA[4*n2+0], ob0 = s_loffB[4*n2+0];
        int oa1 = s_loffA[4*n2+1], ob1 = s_loffB[4*n2+1];
        int oa2 = s_loffA[4*n2+2], ob2 = s_loffB[4*n2+2];
        int oa3 = s_loffA[4*n2+3], ob3 = s_loffB[4*n2+3];

        #pragma unroll
        for (int pr = 0; pr < 2; pr++) {
            unsigned p = pb[pr];
            ull v0 = node2(C[0][0], C[0][1], C[0][2], C[0][3], lds64(p + oa0), lds64(p + ob0));
            ull v1 = node2(C[1][0], C[1][1], C[1][2], C[1][3], lds64(p + oa1), lds64(p + ob1));
            ull v2 = node2(C[2][0], C[2][1], C[2][2], C[2][3], lds64(p + oa2), lds64(p + ob2));
            ull v3 = node2(C[3][0], C[3][1], C[3][2], C[3][3], lds64(p + oa3), lds64(p + ob3));
            ull l1a = node2(C[4][0], C[4][1], C[4][2], C[4][3], v0, v1);
            ull l1b = node2(C[5][0], C[5][1], C[5][2], C[5][3], v2, v3);
            t2[pr][n2] = node2(C[6][0], C[6][1], C[6][2], C[6][3], l1a, l1b);
        }
    }

    ull C28[4], C29[4], C30[4];
    ldcoef(cpb + 28u * 32u, C28[0], C28[1], C28[2], C28[3]);
    ldcoef(cpb + 29u * 32u, C29[0], C29[1], C29[2], C29[3]);
    ldcoef(cpb + 30u * 32u, C30[0], C30[1], C30[2], C30[3]);

    ull res[2];
    #pragma unroll
    for (int pr = 0; pr < 2; pr++) {
        ull l3a = node2(C28[0], C28[1], C28[2], C28[3], t2[pr][0], t2[pr][1]);
        ull l3b = node2(C29[0], C29[1], C29[2], C29[3], t2[pr][2], t2[pr][3]);
        res[pr] = node2(C30[0], C30[1], C30[2], C30[3], l3a, l3b);
    }

    // ---- store: pair -> out[..., lw, 2dp..2dp+1] (8B aligned, coalesced-ish) ----
    float* op = out + (b * K_ + k) * P_ + h0 * 900;
    {
        float lo, hi;
        asm("mov.b64 {%0, %1}, %2;" : "=f"(lo), "=f"(hi) : "l"(res[0]));
        *reinterpret_cast<float2*>(op + lw0 * 30 + 2 * dp0) = make_float2(lo, hi);
    }
    if (q1v < 450) {
        float lo, hi;
        asm("mov.b64 {%0, %1}, %2;" : "=f"(lo), "=f"(hi) : "l"(res[1]));
        *reinterpret_cast<float2*>(op + lw1 * 30 + 2 * dp1) = make_float2(lo, hi);
    }
}

extern "C" void kernel_launch(void* const* d_in, const int* in_sizes, int n_in,
                              void* d_out, int out_size)
{
    const float* x  = nullptr;
    const int*   ia = nullptr;
    const int*   ib = nullptr;
    const float* w0 = nullptr;
    const float* w1 = nullptr;
    const float* w2 = nullptr;
    const float* w3 = nullptr;
    const float* w4 = nullptr;

    for (int i = 0; i < n_in; i++) {
        int sz = in_sizes[i];
        switch (sz) {
            case 393216:   x  = (const float*)d_in[i]; break;   // 4*3*32^3
            case 27648000:                                      // K*P*S*4
                if (!ia) ia = (const int*)d_in[i];
                else     ib = (const int*)d_in[i];
                break;
            case 4096:     w0 = (const float*)d_in[i]; break;
            case 2048:     w1 = (const float*)d_in[i]; break;
            case 1024:     w2 = (const float*)d_in[i]; break;
            case 512:      w3 = (const float*)d_in[i]; break;
            case 256:      w4 = (const float*)d_in[i]; break;
            default: break;
        }
    }

    static int smem_set = 0;
    if (!smem_set) {
        cudaFuncSetAttribute(logic_fused,
                             cudaFuncAttributeMaxDynamicSharedMemorySize,
                             DYN_F * 4);
        smem_set = 1;
    }

    dim3 grid(30, K_, 4);
    logic_fused<<<grid, 256, DYN_F * 4>>>(x, ia, ib, w0, w1, w2, w3, w4,
                                          (float*)d_out);
}

// round 8
// speedup vs baseline: 1.2153x; 1.2153x over previous
#include <cuda_runtime.h>
#include <cuda_bf16.h>

#define K_ 16
#define P_ 27000

// Even tile: x[b, c=0..2, h0:h0+3, 0:32, 0:32], strides c=3072,h=1024,w=32,d=1
// Odd tile : same data shifted by one float (odd[j] = even[j+1])
#define TILE_F 9216                    // floats per tile copy
#define PAD_F  64                      // in-bounds pad for clamped garbage rows
#define DYN_F  (2 * TILE_F + PAD_F)    // 18496 floats = 73984 B dynamic smem

__constant__ float c_MOPS[64] = {
    0,0,0,0,   0,0,0,1,   0,1,0,-1,  0,1,0,0,
    0,0,1,-1,  0,0,1,0,   0,1,1,-2,  0,1,1,-1,
    1,-1,-1,1, 1,-1,-1,2, 1,0,-1,0,  1,0,-1,1,
    1,-1,0,0,  1,-1,0,1,  1,0,0,-1,  1,0,0,0
};

typedef unsigned long long ull;

__device__ __forceinline__ ull fma2(ull a, ull b, ull c) {
    ull d;
    asm("fma.rn.f32x2 %0, %1, %2, %3;" : "=l"(d) : "l"(a), "l"(b), "l"(c));
    return d;
}
// c0 + c1*a + c2*b + c3*a*b (packed over 2 adjacent-d outputs)
__device__ __forceinline__ ull node2(ull c0, ull c1, ull c2, ull c3, ull a, ull b) {
    return fma2(b, fma2(c3, a, c2), fma2(c1, a, c0));
}
__device__ __forceinline__ ull lds64(unsigned a) {
    ull v;
    asm("ld.shared.b64 %0, [%1];" : "=l"(v) : "r"(a));
    return v;
}
__device__ __forceinline__ void ldcoef(unsigned a, ull& c0, ull& c1, ull& c2, ull& c3) {
    asm("ld.shared.v2.u64 {%0,%1}, [%2];" : "=l"(c0), "=l"(c1) : "r"(a));
    asm("ld.shared.v2.u64 {%0,%1}, [%2];" : "=l"(c2), "=l"(c3) : "r"(a + 16));
}

extern __shared__ float s_dyn[];  // [0..9215]=even tile, [9216..18431]=odd, pad

// one leaf node for both output-pairs (rows r and r+16 via +2048B immediate)
__device__ __forceinline__ void leaf2(unsigned cpb, int node, unsigned pb,
                                      int offA, int offB, ull& v0, ull& v1)
{
    ull c0, c1, c2, c3;
    ldcoef(cpb + (unsigned)node * 32u, c0, c1, c2, c3);
    ull a0 = lds64(pb + (unsigned)offA);
    ull a1 = lds64(pb + (unsigned)offA + 2048u);
    ull b0 = lds64(pb + (unsigned)offB);
    ull b1 = lds64(pb + (unsigned)offB + 2048u);
    v0 = node2(c0, c1, c2, c3, a0, b0);
    v1 = node2(c0, c1, c2, c3, a1, b1);
}

__global__ __launch_bounds__(256, 3)
void logic_fused(const float* __restrict__ x,
                 const int* __restrict__ ia, const int* __restrict__ ib,
                 const float* __restrict__ w0, const float* __restrict__ w1,
                 const float* __restrict__ w2, const float* __restrict__ w3,
                 const float* __restrict__ w4,
                 float* __restrict__ out)
{
    __shared__ float4 s_cp[31][2];   // per node: (c0,c0,c1,c1),(c2,c2,c3,c3)
    __shared__ int    s_loffA[16];   // leaf byte offsets (odd parity -> odd tile)
    __shared__ int    s_loffB[16];

    const int h0 = blockIdx.x;   // 0..29
    const int k  = blockIdx.y;
    const int b  = blockIdx.z;
    const int t  = threadIdx.x;

    // ---- prep: tree coefficients, duplicated for f32x2 (threads 0..30) ----
    if (t < 31) {
        const float* wp; int n;
        if      (t < 16) { wp = w0; n = t;      }
        else if (t < 24) { wp = w1; n = t - 16; }
        else if (t < 28) { wp = w2; n = t - 24; }
        else if (t < 30) { wp = w3; n = t - 28; }
        else             { wp = w4; n = 0;      }
        const float* row = wp + (n * K_ + k) * 16;
        float r[16];
        float m = -1e30f;
        #pragma unroll
        for (int o = 0; o < 16; o++) { r[o] = row[o]; m = fmaxf(m, r[o]); }
        float sum = 0.f;
        #pragma unroll
        for (int o = 0; o < 16; o++) { r[o] = __expf(r[o] - m); sum += r[o]; }
        float inv = 1.0f / sum;
        float c0 = 0.f, c1 = 0.f, c2 = 0.f, c3 = 0.f;
        #pragma unroll
        for (int o = 0; o < 16; o++) {
            float p = r[o] * inv;
            c0 = fmaf(p, c_MOPS[4*o + 0], c0);
            c1 = fmaf(p, c_MOPS[4*o + 1], c1);
            c2 = fmaf(p, c_MOPS[4*o + 2], c2);
            c3 = fmaf(p, c_MOPS[4*o + 3], c3);
        }
        s_cp[t][0] = make_float4(c0, c0, c1, c1);
        s_cp[t][1] = make_float4(c2, c2, c3, c3);
    }
    // ---- prep: leaf offsets (threads 32..63); odd parity -> shifted tile ----
    if (t >= 32 && t < 64) {
        int u = t - 32;
        const int* src = (u < 16) ? ia : ib;
        int s = u & 15;
        int base = (k * P_ * 16 + s) * 4;
        int h = src[base + 0];
        int w = src[base + 1];
        int d = src[base + 2];
        int c = src[base + 3];
        int lin = c * 3072 + h * 1024 + w * 32 + d;
        int eff = (lin & 1) ? (TILE_F + lin - 1) : lin;
        if (u < 16) s_loffA[s] = eff * 4;      // byte offsets, 8B-aligned
        else        s_loffB[s] = eff * 4;
    }

    // ---- tile load: even copy + shifted odd copy ----
    {
        const float* src = x + b * 98304 + h0 * 1024;   // x[b,0,h0,0,0]
        float* ev = s_dyn;
        float* od = s_dyn + TILE_F;
        #pragma unroll
        for (int c = 0; c < 3; c++) {
            #pragma unroll
            for (int j = 0; j < 3; j++) {
                int idx = j * 256 + t;
                int e   = idx * 4;
                float4 v = *reinterpret_cast<const float4*>(src + c * 32768 + e);
                float nxt = __shfl_down_sync(0xffffffffu, v.x, 1);
                *reinterpret_cast<float4*>(ev + c * 3072 + e) = v;
                // odd[e+m] = even[e+m+1]; lane31 seam garbage lands at d==31,
                // which no odd-tile gather ever reads.
                *reinterpret_cast<float4*>(od + c * 3072 + e) =
                    make_float4(v.y, v.z, v.w, nxt);
            }
        }
    }
    __syncthreads();

    // ---- compute: conflict-free d-pair mapping ----
    // lane = (half, lp): half = lane>>4, lp = lane&15, dp = min(lp,14)
    // pair0: row0 = 2*warp + half  (0..15)   outputs (row0, 2dp..2dp+1)
    // pair1: row1 = row0 + 16      (16..31)  via +2048B immediate, guard row1<30
    const int lane = t & 31;
    const int warp = t >> 5;
    const int half = lane >> 4;
    const int lp   = lane & 15;
    const int dp   = min(lp, 14);
    const int row0 = 2 * warp + half;
    const int row1 = row0 + 16;

    const unsigned tb  = (unsigned)__cvta_generic_to_shared(s_dyn);
    const unsigned cpb = (unsigned)__cvta_generic_to_shared(&s_cp[0][0]);
    const unsigned pb  = tb + (unsigned)(row0 * 128 + dp * 8);

    ull t2a[4], t2b[4];
    #pragma unroll
    for (int n2 = 0; n2 < 4; n2++) {
        const int2 L0 = make_int2(s_loffA[4*n2+0], s_loffB[4*n2+0]);
        const int2 L1 = make_int2(s_loffA[4*n2+1], s_loffB[4*n2+1]);
        const int2 L2 = make_int2(s_loffA[4*n2+2], s_loffB[4*n2+2]);
        const int2 L3 = make_int2(s_loffA[4*n2+3], s_loffB[4*n2+3]);

        ull p0, p1, q0, q1;
        leaf2(cpb, 4*n2 + 0, pb, L0.x, L0.y, p0, p1);
        leaf2(cpb, 4*n2 + 1, pb, L1.x, L1.y, q0, q1);
        ull m0, m1;
        {
            ull c0, c1, c2, c3;
            ldcoef(cpb + (unsigned)(16 + 2*n2) * 32u, c0, c1, c2, c3);
            m0 = node2(c0, c1, c2, c3, p0, q0);
            m1 = node2(c0, c1, c2, c3, p1, q1);
        }
        leaf2(cpb, 4*n2 + 2, pb, L2.x, L2.y, p0, p1);
        leaf2(cpb, 4*n2 + 3, pb, L3.x, L3.y, q0, q1);
        ull n0, n1;
        {
            ull c0, c1, c2, c3;
            ldcoef(cpb + (unsigned)(17 + 2*n2) * 32u, c0, c1, c2, c3);
            n0 = node2(c0, c1, c2, c3, p0, q0);
            n1 = node2(c0, c1, c2, c3, p1, q1);
        }
        {
            ull c0, c1, c2, c3;
            ldcoef(cpb + (unsigned)(24 + n2) * 32u, c0, c1, c2, c3);
            t2a[n2] = node2(c0, c1, c2, c3, m0, n0);
            t2b[n2] = node2(c0, c1, c2, c3, m1, n1);
        }
    }

    ull resA, resB;
    {
        ull d0, d1, d2, d3, e0, e1, e2, e3, f0, f1, f2, f3;
        ldcoef(cpb + 28u * 32u, d0, d1, d2, d3);
        ldcoef(cpb + 29u * 32u, e0, e1, e2, e3);
        ldcoef(cpb + 30u * 32u, f0, f1, f2, f3);
        ull xa = node2(d0, d1, d2, d3, t2a[0], t2a[1]);
        ull ya = node2(e0, e1, e2, e3, t2a[2], t2a[3]);
        resA = node2(f0, f1, f2, f3, xa, ya);
        ull xb = node2(d0, d1, d2, d3, t2b[0], t2b[1]);
        ull yb = node2(e0, e1, e2, e3, t2b[2], t2b[3]);
        resB = node2(f0, f1, f2, f3, xb, yb);
    }

    // ---- store: float2 per pair, coalesced over dp ----
    if (lp < 15) {
        float* op = out + (b * K_ + k) * P_ + h0 * 900;
        {
            float lo, hi;
            asm("mov.b64 {%0, %1}, %2;" : "=f"(lo), "=f"(hi) : "l"(resA));
            *reinterpret_cast<float2*>(op + row0 * 30 + 2 * dp) = make_float2(lo, hi);
        }
        if (row1 < 30) {
            float lo, hi;
            asm("mov.b64 {%0, %1}, %2;" : "=f"(lo), "=f"(hi) : "l"(resB));
            *reinterpret_cast<float2*>(op + row1 * 30 + 2 * dp) = make_float2(lo, hi);
        }
    }
}

extern "C" void kernel_launch(void* const* d_in, const int* in_sizes, int n_in,
                              void* d_out, int out_size)
{
    const float* x  = nullptr;
    const int*   ia = nullptr;
    const int*   ib = nullptr;
    const float* w0 = nullptr;
    const float* w1 = nullptr;
    const float* w2 = nullptr;
    const float* w3 = nullptr;
    const float* w4 = nullptr;

    for (int i = 0; i < n_in; i++) {
        int sz = in_sizes[i];
        switch (sz) {
            case 393216:   x  = (const float*)d_in[i]; break;   // 4*3*32^3
            case 27648000:                                      // K*P*S*4
                if (!ia) ia = (const int*)d_in[i];
                else     ib = (const int*)d_in[i];
                break;
            case 4096:     w0 = (const float*)d_in[i]; break;
            case 2048:     w1 = (const float*)d_in[i]; break;
            case 1024:     w2 = (const float*)d_in[i]; break;
            case 512:      w3 = (const float*)d_in[i]; break;
            case 256:      w4 = (const float*)d_in[i]; break;
            default: break;
        }
    }

    static int smem_set = 0;
    if (!smem_set) {
        cudaFuncSetAttribute(logic_fused,
                             cudaFuncAttributeMaxDynamicSharedMemorySize,
                             DYN_F * 4);
        smem_set = 1;
    }

    dim3 grid(30, K_, 4);
    logic_fused<<<grid, 256, DYN_F * 4>>>(x, ia, ib, w0, w1, w2, w3, w4,
                                          (float*)d_out);
}

// round 9
// speedup vs baseline: 1.3530x; 1.1133x over previous
#include <cuda_runtime.h>
#include <cuda_bf16.h>

#define K_ 16
#define P_ 27000

// Tile: x[b, c=0..2, h0:h0+3, 0:32, 0:32], strides c=3072,h=1024,w=32,d=1
#define TILE_F 9216
#define PAD_F  64                  // halo for compute-only rows 30/31 overflow
#define DYN_F  (TILE_F + PAD_F)    // 9280 floats = 37120 B dynamic smem

__constant__ float c_MOPS[64] = {
    0,0,0,0,   0,0,0,1,   0,1,0,-1,  0,1,0,0,
    0,0,1,-1,  0,0,1,0,   0,1,1,-2,  0,1,1,-1,
    1,-1,-1,1, 1,-1,-1,2, 1,0,-1,0,  1,0,-1,1,
    1,-1,0,0,  1,-1,0,1,  1,0,0,-1,  1,0,0,0
};

typedef unsigned long long ull;

__device__ __forceinline__ ull fma2(ull a, ull b, ull c) {
    ull d;
    asm("fma.rn.f32x2 %0, %1, %2, %3;" : "=l"(d) : "l"(a), "l"(b), "l"(c));
    return d;
}
// c0 + c1*a + c2*b + c3*a*b, packed over 2 outputs
__device__ __forceinline__ ull node2(ull c0, ull c1, ull c2, ull c3, ull a, ull b) {
    return fma2(b, fma2(c3, a, c2), fma2(c1, a, c0));
}
__device__ __forceinline__ ull pack2(float lo, float hi) {
    ull r;
    asm("mov.b64 %0, {%1, %2};" : "=l"(r) : "f"(lo), "f"(hi));
    return r;
}
__device__ __forceinline__ float ldsf(unsigned a) {
    float v;
    asm("ld.shared.f32 %0, [%1];" : "=f"(v) : "r"(a));
    return v;
}
__device__ __forceinline__ void ldcoef(unsigned a, ull& c0, ull& c1, ull& c2, ull& c3) {
    asm("ld.shared.v2.u64 {%0,%1}, [%2];" : "=l"(c0), "=l"(c1) : "r"(a));
    asm("ld.shared.v2.u64 {%0,%1}, [%2];" : "=l"(c2), "=l"(c3) : "r"(a + 16));
}

extern __shared__ float s_dyn[];   // tile + pad

// One leaf node evaluated for both output pairs.
// Rows (warp, warp+8) -> pair0 ; (warp+16, warp+24) -> pair1, via immediates.
__device__ __forceinline__ void leaf2(unsigned cpb, int node, unsigned tb,
                                      int offA, int offB, ull& v0, ull& v1)
{
    unsigned aA = tb + (unsigned)offA;
    unsigned aB = tb + (unsigned)offB;
    float a0 = ldsf(aA);            float b0 = ldsf(aB);
    float a1 = ldsf(aA + 1024u);    float b1 = ldsf(aB + 1024u);
    float a2 = ldsf(aA + 2048u);    float b2 = ldsf(aB + 2048u);
    float a3 = ldsf(aA + 3072u);    float b3 = ldsf(aB + 3072u);
    ull c0, c1, c2, c3;
    ldcoef(cpb + (unsigned)node * 32u, c0, c1, c2, c3);
    v0 = node2(c0, c1, c2, c3, pack2(a0, a1), pack2(b0, b1));
    v1 = node2(c0, c1, c2, c3, pack2(a2, a3), pack2(b2, b3));
}

__global__ __launch_bounds__(256, 4)
void logic_fused(const float* __restrict__ x,
                 const int* __restrict__ ia, const int* __restrict__ ib,
                 const float* __restrict__ w0, const float* __restrict__ w1,
                 const float* __restrict__ w2, const float* __restrict__ w3,
                 const float* __restrict__ w4,
                 float* __restrict__ out)
{
    __shared__ float4 s_cp[31][2];   // (c0,c0,c1,c1),(c2,c2,c3,c3) per node
    __shared__ int2   s_loff[16];    // leaf byte offsets (A, B)

    const int h0 = blockIdx.x;   // 0..29
    const int k  = blockIdx.y;
    const int b  = blockIdx.z;
    const int t  = threadIdx.x;

    // ---- prep: coefficients duplicated for f32x2 (threads 0..30) ----
    if (t < 31) {
        const float* wp; int n;
        if      (t < 16) { wp = w0; n = t;      }
        else if (t < 24) { wp = w1; n = t - 16; }
        else if (t < 28) { wp = w2; n = t - 24; }
        else if (t < 30) { wp = w3; n = t - 28; }
        else             { wp = w4; n = 0;      }
        const float* row = wp + (n * K_ + k) * 16;
        float r[16];
        float m = -1e30f;
        #pragma unroll
        for (int o = 0; o < 16; o++) { r[o] = row[o]; m = fmaxf(m, r[o]); }
        float sum = 0.f;
        #pragma unroll
        for (int o = 0; o < 16; o++) { r[o] = __expf(r[o] - m); sum += r[o]; }
        float inv = 1.0f / sum;
        float c0 = 0.f, c1 = 0.f, c2 = 0.f, c3 = 0.f;
        #pragma unroll
        for (int o = 0; o < 16; o++) {
            float p = r[o] * inv;
            c0 = fmaf(p, c_MOPS[4*o + 0], c0);
            c1 = fmaf(p, c_MOPS[4*o + 1], c1);
            c2 = fmaf(p, c_MOPS[4*o + 2], c2);
            c3 = fmaf(p, c_MOPS[4*o + 3], c3);
        }
        s_cp[t][0] = make_float4(c0, c0, c1, c1);
        s_cp[t][1] = make_float4(c2, c2, c3, c3);
    }
    // ---- prep: leaf byte offsets (threads 32..63) ----
    if (t >= 32 && t < 64) {
        int u = t - 32;
        const int* src = (u < 16) ? ia : ib;
        int s = u & 15;
        int base = (k * P_ * 16 + s) * 4;
        int h = src[base + 0];
        int w = src[base + 1];
        int d = src[base + 2];
        int c = src[base + 3];
        int off = (c * 3072 + h * 1024 + w * 32 + d) * 4;   // byte offset
        if (u < 16) s_loff[s].x = off;
        else        s_loff[s].y = off;
    }

    // ---- tile load: 3 contiguous slabs, pure float4 copies ----
    {
        const float* src = x + b * 98304 + h0 * 1024;   // x[b,0,h0,0,0]
        #pragma unroll
        for (int c = 0; c < 3; c++) {
            #pragma unroll
            for (int j = 0; j < 3; j++) {
                int e = (j * 256 + t) * 4;
                float4 v = *reinterpret_cast<const float4*>(src + c * 32768 + e);
                *reinterpret_cast<float4*>(s_dyn + c * 3072 + e) = v;
            }
        }
    }
    __syncthreads();

    // ---- compute: lane = d (clamped), rows warp+{0,8,16,24} ----
    const int lane = t & 31;
    const int warp = t >> 5;
    const int ld   = min(lane, 29);   // d + leaf_d must stay < 32

    const unsigned tb  = (unsigned)__cvta_generic_to_shared(s_dyn)
                       + 4u * (unsigned)(warp * 32 + ld);
    const unsigned cpb = (unsigned)__cvta_generic_to_shared(&s_cp[0][0]);

    ull t2a[4], t2b[4];
    #pragma unroll
    for (int n2 = 0; n2 < 4; n2++) {
        const int2 L0 = s_loff[4*n2 + 0];
        const int2 L1 = s_loff[4*n2 + 1];
        const int2 L2 = s_loff[4*n2 + 2];
        const int2 L3 = s_loff[4*n2 + 3];

        ull p0, p1, q0, q1;
        leaf2(cpb, 4*n2 + 0, tb, L0.x, L0.y, p0, p1);
        leaf2(cpb, 4*n2 + 1, tb, L1.x, L1.y, q0, q1);
        ull m0, m1;
        {
            ull c0, c1, c2, c3;
            ldcoef(cpb + (unsigned)(16 + 2*n2) * 32u, c0, c1, c2, c3);
            m0 = node2(c0, c1, c2, c3, p0, q0);
            m1 = node2(c0, c1, c2, c3, p1, q1);
        }
        leaf2(cpb, 4*n2 + 2, tb, L2.x, L2.y, p0, p1);
        leaf2(cpb, 4*n2 + 3, tb, L3.x, L3.y, q0, q1);
        ull n0, n1;
        {
            ull c0, c1, c2, c3;
            ldcoef(cpb + (unsigned)(17 + 2*n2) * 32u, c0, c1, c2, c3);
            n0 = node2(c0, c1, c2, c3, p0, q0);
            n1 = node2(c0, c1, c2, c3, p1, q1);
        }
        {
            ull c0, c1, c2, c3;
            ldcoef(cpb + (unsigned)(24 + n2) * 32u, c0, c1, c2, c3);
            t2a[n2] = node2(c0, c1, c2, c3, m0, n0);
            t2b[n2] = node2(c0, c1, c2, c3, m1, n1);
        }
    }

    ull resA, resB;
    {
        ull d0, d1, d2, d3, e0, e1, e2, e3, f0, f1, f2, f3;
        ldcoef(cpb + 28u * 32u, d0, d1, d2, d3);
        ldcoef(cpb + 29u * 32u, e0, e1, e2, e3);
        ldcoef(cpb + 30u * 32u, f0, f1, f2, f3);
        ull xa = node2(d0, d1, d2, d3, t2a[0], t2a[1]);
        ull ya = node2(e0, e1, e2, e3, t2a[2], t2a[3]);
        resA = node2(f0, f1, f2, f3, xa, ya);            // rows warp, warp+8
        ull xb = node2(d0, d1, d2, d3, t2b[0], t2b[1]);
        ull yb = node2(e0, e1, e2, e3, t2b[2], t2b[3]);
        resB = node2(f0, f1, f2, f3, xb, yb);            // rows warp+16, warp+24
    }

    // ---- store: 4 scalar rows, coalesced over lane ----
    if (lane < 30) {
        float* op = out + (b * K_ + k) * P_ + h0 * 900 + warp * 30 + lane;
        float r0, r1, r2, r3;
        asm("mov.b64 {%0, %1}, %2;" : "=f"(r0), "=f"(r1) : "l"(resA));
        asm("mov.b64 {%0, %1}, %2;" : "=f"(r2), "=f"(r3) : "l"(resB));
        op[0]   = r0;          // row warp        (<= 7)
        op[240] = r1;          // row warp + 8    (<= 15)
        op[480] = r2;          // row warp + 16   (<= 23)
        if (warp < 6) op[720] = r3;   // row warp + 24 < 30
    }
}

extern "C" void kernel_launch(void* const* d_in, const int* in_sizes, int n_in,
                              void* d_out, int out_size)
{
    const float* x  = nullptr;
    const int*   ia = nullptr;
    const int*   ib = nullptr;
    const float* w0 = nullptr;
    const float* w1 = nullptr;
    const float* w2 = nullptr;
    const float* w3 = nullptr;
    const float* w4 = nullptr;

    for (int i = 0; i < n_in; i++) {
        int sz = in_sizes[i];
        switch (sz) {
            case 393216:   x  = (const float*)d_in[i]; break;   // 4*3*32^3
            case 27648000:                                      // K*P*S*4
                if (!ia) ia = (const int*)d_in[i];
                else     ib = (const int*)d_in[i];
                break;
            case 4096:     w0 = (const float*)d_in[i]; break;
            case 2048:     w1 = (const float*)d_in[i]; break;
            case 1024:     w2 = (const float*)d_in[i]; break;
            case 512:      w3 = (const float*)d_in[i]; break;
            case 256:      w4 = (const float*)d_in[i]; break;
            default: break;
        }
    }

    dim3 grid(30, K_, 4);
    logic_fused<<<grid, 256, DYN_F * 4>>>(x, ia, ib, w0, w1, w2, w3, w4,
                                          (float*)d_out);
}